// round 1
// baseline (speedup 1.0000x reference)
#include <cuda_runtime.h>

#define BATCH 16384

// ---------------- static scratch (device globals; no allocations) ----------------
__device__ float g_bufA[(long long)BATCH * 6000]; // 675 / 5400 / 6000 per batch
__device__ float g_bufB[(long long)BATCH * 3000]; // 450 / 3000 / 3000
__device__ float g_bufC[(long long)BATCH * 1875]; // 90 / 1250 / 1875
__device__ float g_x1 [(long long)BATCH * 2250];  // stage-0 output
__device__ float g_x2 [(long long)BATCH * 3750];  // stage-1 output

// ---------------- tiled GEMM with fused im2col / semi-linear gather ----------------
constexpr int BM = 128, BN = 128, BK = 16, TM = 8, TN = 8, NT = 256;

// MODE 0: conv over H.  m=(b, oh*OW+ow), k=(ic*KH+kh).
//   A index = b*abstride + ic*IH*IW + (oh+kh-PH)*IW + ow   (zero outside [0,IH))
//   Out index = b*N*SP + n*SP + s                          (NCHW)
// MODE 1: semi-linear. m=(b, r) with r=(c*H+h), k over last axis (size K).
//   A index = b*abstride + r*K + k
//   Out index = b*SP*N + r*N + n                           (-> NCHW with W=N)
template <int MODE, int KH>
__global__ __launch_bounds__(NT, 2)
void gemm_layer(const float* __restrict__ A, const float* __restrict__ W,
                const float* __restrict__ bias, float* __restrict__ Out,
                int N, int K, int IH, int IW, int PH, int SP, int OW,
                int abstride, int relu, int accum)
{
    __shared__ __align__(16) float sA[BK][BM];
    __shared__ __align__(16) float sB[BK][BN + 4];

    const int tid = threadIdx.x;
    const int m0  = blockIdx.x * BM;
    const int n0  = blockIdx.y * BN;

    // ---- per-thread A-load slot: fixed m, k-slots {a_k0 + 2j} ----
    const int a_ml = tid & 127;
    const int a_m  = m0 + a_ml;
    const int a_k0 = tid >> 7;            // 0 or 1
    const int b_   = a_m / SP;
    const int s_   = a_m - b_ * SP;
    const float* Abase;
    int oh_ = 0;
    if (MODE == 0) {
        oh_ = s_ / OW;
        const int ow_ = s_ - oh_ * OW;
        Abase = A + (long long)b_ * abstride + ow_;
    } else {
        Abase = A + (long long)b_ * abstride + (long long)s_ * K;
    }
    const int IHW = IH * IW;

    float acc[TM][TN];
#pragma unroll
    for (int i = 0; i < TM; i++)
#pragma unroll
        for (int j = 0; j < TN; j++) acc[i][j] = 0.0f;

    const int tn = tid & 15;   // 16 n-groups of 8
    const int tm = tid >> 4;   // 16 m-groups of 8

    for (int k0 = 0; k0 < K; k0 += BK) {
        // ---- stage A tile: sA[k][m] ----
#pragma unroll
        for (int j = 0; j < 8; j++) {
            const int kl = a_k0 + 2 * j;
            const int k  = k0 + kl;
            float v = 0.0f;
            if (k < K) {
                if (MODE == 0) {
                    const int ic = k / KH;
                    const int kh = k - ic * KH;
                    const int ih = oh_ + kh - PH;
                    if ((unsigned)ih < (unsigned)IH)
                        v = Abase[ic * IHW + ih * IW];
                } else {
                    v = Abase[k];
                }
            }
            sA[kl][a_ml] = v;
        }
        // ---- stage B tile: sB[k][n], W is [N][K] row-major ----
#pragma unroll
        for (int j = 0; j < 8; j++) {
            const int idx = tid + j * NT;
            const int kl  = idx & 15;
            const int n   = idx >> 4;
            const int k   = k0 + kl;
            const int nn  = n0 + n;
            float v = 0.0f;
            if (k < K && nn < N) v = W[(long long)nn * K + k];
            sB[kl][n] = v;
        }
        __syncthreads();

#pragma unroll
        for (int kk = 0; kk < BK; kk++) {
            float av[TM], bv[TN];
            const float4 a0 = *(const float4*)&sA[kk][tm * TM];
            const float4 a1 = *(const float4*)&sA[kk][tm * TM + 4];
            const float4 b0 = *(const float4*)&sB[kk][tn * TN];
            const float4 b1 = *(const float4*)&sB[kk][tn * TN + 4];
            av[0]=a0.x; av[1]=a0.y; av[2]=a0.z; av[3]=a0.w;
            av[4]=a1.x; av[5]=a1.y; av[6]=a1.z; av[7]=a1.w;
            bv[0]=b0.x; bv[1]=b0.y; bv[2]=b0.z; bv[3]=b0.w;
            bv[4]=b1.x; bv[5]=b1.y; bv[6]=b1.z; bv[7]=b1.w;
#pragma unroll
            for (int i = 0; i < TM; i++)
#pragma unroll
                for (int j = 0; j < TN; j++)
                    acc[i][j] = fmaf(av[i], bv[j], acc[i][j]);
        }
        __syncthreads();
    }

    // ---- epilogue: bias (+relu) (+accumulate) ----
#pragma unroll
    for (int i = 0; i < TM; i++) {
        const int m = m0 + tm * TM + i;
        const int b = m / SP;
        const int s = m - b * SP;
#pragma unroll
        for (int j = 0; j < TN; j++) {
            const int n = n0 + tn * TN + j;
            if (n < N) {
                float v = acc[i][j] + bias[n];
                if (relu) v = fmaxf(v, 0.0f);
                long long o;
                if (MODE == 0) o = (long long)b * N * SP + (long long)n * SP + s;
                else           o = (long long)b * SP * N + (long long)s * N + n;
                if (accum) Out[o] += v;
                else       Out[o]  = v;
            }
        }
    }
}

// ---------------- host-side launch helpers ----------------
static void conv_launch(int KH, const float* A, const float* W, const float* b, float* O,
                        int IC, int IH, int IW, int OC, int PH, int accum)
{
    const int OH = IH + 2 * PH - KH + 1;
    const int OW = IW;
    const int SP = OH * OW;
    const int K  = IC * KH;
    const int N  = OC;
    const long long M = (long long)BATCH * SP;           // always multiple of 128
    dim3 grid((unsigned)(M / BM), (unsigned)((N + BN - 1) / BN));
    const int abstride = IC * IH * IW;
    switch (KH) {
    case 1: gemm_layer<0,1><<<grid, NT>>>(A, W, b, O, N, K, IH, IW, PH, SP, OW, abstride, 0, accum); break;
    case 2: gemm_layer<0,2><<<grid, NT>>>(A, W, b, O, N, K, IH, IW, PH, SP, OW, abstride, 0, accum); break;
    case 3: gemm_layer<0,3><<<grid, NT>>>(A, W, b, O, N, K, IH, IW, PH, SP, OW, abstride, 0, accum); break;
    }
}

static void sl_launch(const float* A, const float* W, const float* b, float* O,
                      int R, int Win, int N, int relu)
{
    const int SP = R;          // rows per batch (C*H)
    const int K  = Win;
    const long long M = (long long)BATCH * SP;
    dim3 grid((unsigned)(M / BM), (unsigned)((N + BN - 1) / BN));
    gemm_layer<1,1><<<grid, NT>>>(A, W, b, O, N, K, 1, 1, 0, SP, 1, R * K, relu, 0);
}

extern "C" void kernel_launch(void* const* d_in, const int* in_sizes, int n_in,
                              void* d_out, int out_size)
{
    (void)in_sizes; (void)n_in; (void)out_size;
    const float* x    = (const float*)d_in[0];
    const float* w0a  = (const float*)d_in[1];  const float* b0a  = (const float*)d_in[2];
    const float* wl0  = (const float*)d_in[3];  const float* bl0  = (const float*)d_in[4];
    const float* w0b  = (const float*)d_in[5];  const float* b0b  = (const float*)d_in[6];
    const float* w0c  = (const float*)d_in[7];  const float* b0c  = (const float*)d_in[8];
    const float* wr0  = (const float*)d_in[9];  const float* br0  = (const float*)d_in[10];
    const float* w1   = (const float*)d_in[11]; const float* b1   = (const float*)d_in[12];
    const float* wl1  = (const float*)d_in[13]; const float* bl1  = (const float*)d_in[14];
    const float* w2   = (const float*)d_in[15]; const float* b2   = (const float*)d_in[16];
    const float* wa   = (const float*)d_in[17]; const float* ba   = (const float*)d_in[18];
    const float* wra  = (const float*)d_in[19]; const float* bra  = (const float*)d_in[20];
    const float* w0   = (const float*)d_in[21]; const float* b0   = (const float*)d_in[22];
    const float* wl2  = (const float*)d_in[23]; const float* bl2  = (const float*)d_in[24];
    const float* w0b2 = (const float*)d_in[25]; const float* b0b2 = (const float*)d_in[26];
    const float* w0c2 = (const float*)d_in[27]; const float* b0c2 = (const float*)d_in[28];
    const float* wr02 = (const float*)d_in[29]; const float* br02 = (const float*)d_in[30];
    float* out = (float*)d_out;

    float *A, *Bb, *C, *x1, *x2;
    cudaGetSymbolAddress((void**)&A,  g_bufA);
    cudaGetSymbolAddress((void**)&Bb, g_bufB);
    cudaGetSymbolAddress((void**)&C,  g_bufC);
    cudaGetSymbolAddress((void**)&x1, g_x1);
    cudaGetSymbolAddress((void**)&x2, g_x2);

    // ---- stage 0 ----
    conv_launch(3, x,  w0a, b0a, A,  1, 5, 27,  5, 1, 0);   // (B,5,5,27)
    sl_launch  (A, wl0, bl0, Bb, 25, 27, 18, 1);            // relu -> (B,5,5,18)
    conv_launch(3, Bb, w0b, b0b, x1, 5, 5, 18, 25, 1, 0);   // z -> x1 (B,25,5,18)
    sl_launch  (x, wr0, br0, C, 5, 27, 18, 0);              // (B,1,5,18)
    conv_launch(1, C,  w0c, b0c, x1, 1, 5, 18, 25, 0, 1);   // += y

    // ---- stage 1 ----
    conv_launch(2, x1, w1, b1, A, 25, 5, 18, 75, 0, 0);     // (B,75,4,18)
    sl_launch  (A, wl1, bl1, Bb, 300, 18, 10, 1);           // relu -> (B,75,4,10)
    conv_launch(2, Bb, w2, b2, x2, 75, 4, 10, 125, 0, 0);   // z -> x2 (B,125,3,10)
    sl_launch  (x1, wra, bra, C, 125, 18, 10, 0);           // (B,25,5,10)
    conv_launch(3, C, wa, ba, x2, 25, 5, 10, 125, 0, 1);    // += y

    // ---- stage 2 ----
    conv_launch(2, x2, w0, b0, A, 125, 3, 10, 300, 0, 0);   // (B,300,2,10)
    sl_launch  (A, wl2, bl2, Bb, 600, 10, 5, 1);            // relu -> (B,300,2,5)
    conv_launch(2, Bb, w0b2, b0b2, out, 300, 2, 5, 512, 0, 0); // z -> out (B,512,1,5)
    sl_launch  (x2, wr02, br02, C, 375, 10, 5, 0);          // (B,125,3,5)
    conv_launch(3, C, w0c2, b0c2, out, 125, 3, 5, 512, 0, 1); // += y
}

// round 2
// speedup vs baseline: 1.6118x; 1.6118x over previous
#include <cuda_runtime.h>

#define BATCH 16384

// ---------------- static scratch (device globals; no allocations) ----------------
__device__ float g_bufA[(long long)BATCH * 6000];
__device__ float g_bufB[(long long)BATCH * 3000];
__device__ float g_bufC[(long long)BATCH * 1875];
__device__ float g_x1 [(long long)BATCH * 2250];
__device__ float g_x2 [(long long)BATCH * 3750];

// Packed fp32x2 FMA (Blackwell FFMA2). d = a*b + d elementwise on 2 lanes.
__device__ __forceinline__ void ffma2(float2& d, const float2& a, const float2& b) {
    unsigned long long& dd = reinterpret_cast<unsigned long long&>(d);
    const unsigned long long& aa = reinterpret_cast<const unsigned long long&>(a);
    const unsigned long long& bb = reinterpret_cast<const unsigned long long&>(b);
    asm("fma.rn.f32x2 %0, %1, %2, %0;" : "+l"(dd) : "l"(aa), "l"(bb));
}

// ---------------- fully-templated GEMM with fused im2col / semi-linear gather ----
// MODE 0: conv over H.  m=(b, oh*OW+ow), k=(ic*KH+kh). Output NCHW.
// MODE 1: semi-linear.  m=(b, r) r=(c*H+h), k over last axis. Output (...,N) = NCHW.
template<int MODE,int KH,int BM,int BN,int BK,int TM,int TN,int N,int K,int RELU,int ACCUM>
__global__ void __launch_bounds__((BM/TM)*(BN/TN), 2)
gemm(const float* __restrict__ A, const float* __restrict__ W,
     const float* __restrict__ bias, float* __restrict__ Out,
     int IH, int IW, int PH, int SP, int OW, int abstride)
{
    constexpr int NT    = (BM/TM)*(BN/TN);
    constexpr int KITER = (K + BK - 1) / BK;
    constexpr bool KG   = (K % BK) != 0;          // need k<K guard
    constexpr bool NG   = (N % BN) != 0;          // need n<N guard
    constexpr int ROWS  = (BM > NT) ? BM/NT : 1;  // A rows per thread
    constexpr int KSL   = (NT > BM) ? NT/BM : 1;  // k-slot stride groups
    constexpr int AJ    = BK / KSL;               // A k-loads per row per thread
    static_assert(BK % KSL == 0, "BK divisible by k-slot groups");
    static_assert(TN % 2 == 0, "TN even for f32x2 packing");

    __shared__ __align__(16) float sA[BK][2*BM];      // A duplicated pairs
    __shared__ __align__(16) float sB[BK][BN + 4];    // +4 keeps rows 16B-aligned

    const int tid = threadIdx.x;
    const int m0  = blockIdx.x * BM;
    const int n0  = blockIdx.y * BN;

    // ---- A row descriptors (fixed m per thread-slot, k varies) ----
    const int a_k0 = (NT > BM) ? (tid / BM) : 0;
    const float* Abase[ROWS];
    int oh_[ROWS], aml[ROWS];
    const int IHW = IH * IW;
#pragma unroll
    for (int r = 0; r < ROWS; r++) {
        const int ml = (NT >= BM) ? (tid % BM) : (tid + r * NT);
        aml[r] = ml;
        const int m = m0 + ml;
        const int b = m / SP;
        const int s = m - b * SP;
        if (MODE == 0) {
            const int oh = s / OW;
            const int ow = s - oh * OW;
            oh_[r] = oh;
            Abase[r] = A + (long long)b * abstride + ow;
        } else {
            oh_[r] = 0;
            Abase[r] = A + (long long)b * abstride + (long long)s * K;
        }
    }

    const int tn = tid % (BN/TN);
    const int tm = tid / (BN/TN);

    float2 acc[TM][TN/2];
#pragma unroll
    for (int i = 0; i < TM; i++)
#pragma unroll
        for (int j = 0; j < TN/2; j++) acc[i][j] = make_float2(0.f, 0.f);

    for (int kt = 0; kt < KITER; kt++) {
        const int k0 = kt * BK;
        // ---- stage A (duplicated pairs for f32x2) ----
#pragma unroll
        for (int r = 0; r < ROWS; r++) {
#pragma unroll
            for (int j = 0; j < AJ; j++) {
                const int kl = a_k0 + KSL * j;
                const int k  = k0 + kl;
                float v = 0.0f;
                if (!KG || k < K) {
                    if (MODE == 0) {
                        const int ic = k / KH;
                        const int kh = k - ic * KH;
                        const int ih = oh_[r] + kh - PH;
                        if ((unsigned)ih < (unsigned)IH)
                            v = Abase[r][ic * IHW + ih * IW];
                    } else {
                        v = Abase[r][k];
                    }
                }
                *(float2*)&sA[kl][2 * aml[r]] = make_float2(v, v);
            }
        }
        // ---- stage B: W is [N][K] row-major ----
        constexpr int BTOT = BK * BN;
        constexpr int BIT  = (BTOT + NT - 1) / NT;
#pragma unroll
        for (int t = 0; t < BIT; t++) {
            const int idx = tid + t * NT;
            if (BTOT % NT == 0 || idx < BTOT) {
                const int kl = idx % BK;
                const int n  = idx / BK;
                const int k  = k0 + kl;
                const int nn = n0 + n;
                float v = 0.0f;
                if ((!KG || k < K) && (!NG || nn < N)) v = W[nn * K + k];
                sB[kl][n] = v;
            }
        }
        __syncthreads();

#pragma unroll
        for (int kk = 0; kk < BK; kk++) {
            float2 a2[TM], b2[TN/2];
            // A: 2*TM duplicated floats, 64B-aligned -> float4 loads
            {
                const float4* pa = (const float4*)&sA[kk][2 * tm * TM];
#pragma unroll
                for (int q = 0; q < TM/2; q++) {
                    const float4 t4 = pa[q];
                    a2[2*q]   = make_float2(t4.x, t4.y);
                    a2[2*q+1] = make_float2(t4.z, t4.w);
                }
            }
            // B: TN floats
            if constexpr (TN % 4 == 0) {
                const float4* pb = (const float4*)&sB[kk][tn * TN];
#pragma unroll
                for (int q = 0; q < TN/4; q++) {
                    const float4 t4 = pb[q];
                    b2[2*q]   = make_float2(t4.x, t4.y);
                    b2[2*q+1] = make_float2(t4.z, t4.w);
                }
            } else {
                const float2* pb = (const float2*)&sB[kk][tn * TN];
#pragma unroll
                for (int q = 0; q < TN/2; q++) b2[q] = pb[q];
            }
#pragma unroll
            for (int i = 0; i < TM; i++)
#pragma unroll
                for (int j = 0; j < TN/2; j++)
                    ffma2(acc[i][j], a2[i], b2[j]);
        }
        __syncthreads();
    }

    // ---- epilogue: bias (+relu) (+accumulate) ----
#pragma unroll
    for (int i = 0; i < TM; i++) {
        const int m = m0 + tm * TM + i;
        const int b = m / SP;
        const int s = m - b * SP;
#pragma unroll
        for (int j = 0; j < TN/2; j++) {
#pragma unroll
            for (int h = 0; h < 2; h++) {
                const int n = n0 + tn * TN + 2*j + h;
                if (!NG || n < N) {
                    float v = (h ? acc[i][j].y : acc[i][j].x) + bias[n];
                    if (RELU) v = fmaxf(v, 0.0f);
                    long long o;
                    if (MODE == 0) o = (long long)b * (N * SP) + (long long)n * SP + s;
                    else           o = (long long)b * (SP * N) + (long long)s * N + n;
                    if (ACCUM) Out[o] += v; else Out[o] = v;
                }
            }
        }
    }
}

// ---------------- host-side typed launchers ----------------
template<int KH,int BN,int BK,int TM,int TN,int N,int K,int ACCUM>
static void conv(const float* A, const float* W, const float* b, float* O,
                 int IH, int IW, int PH)
{
    constexpr int BM = 128;
    constexpr int IC = K / KH;
    const int OH = IH + 2*PH - KH + 1, OW = IW, SP = OH * OW;
    dim3 g((unsigned)((long long)BATCH * SP / BM), (N + BN - 1) / BN);
    gemm<0,KH,BM,BN,BK,TM,TN,N,K,0,ACCUM><<<g, (BM/TM)*(BN/TN)>>>(
        A, W, b, O, IH, IW, PH, SP, OW, IC*IH*IW);
}

template<int BN,int BK,int TM,int TN,int N,int K,int RELU>
static void sl(const float* A, const float* W, const float* b, float* O, int SP)
{
    constexpr int BM = 128;
    dim3 g((unsigned)((long long)BATCH * SP / BM), (N + BN - 1) / BN);
    gemm<1,1,BM,BN,BK,TM,TN,N,K,RELU,0><<<g, (BM/TM)*(BN/TN)>>>(
        A, W, b, O, 1, 1, 0, SP, 1, SP*K);
}

extern "C" void kernel_launch(void* const* d_in, const int* in_sizes, int n_in,
                              void* d_out, int out_size)
{
    (void)in_sizes; (void)n_in; (void)out_size;
    const float* x    = (const float*)d_in[0];
    const float* w0a  = (const float*)d_in[1];  const float* b0a  = (const float*)d_in[2];
    const float* wl0  = (const float*)d_in[3];  const float* bl0  = (const float*)d_in[4];
    const float* w0b  = (const float*)d_in[5];  const float* b0b  = (const float*)d_in[6];
    const float* w0c  = (const float*)d_in[7];  const float* b0c  = (const float*)d_in[8];
    const float* wr0  = (const float*)d_in[9];  const float* br0  = (const float*)d_in[10];
    const float* w1   = (const float*)d_in[11]; const float* b1   = (const float*)d_in[12];
    const float* wl1  = (const float*)d_in[13]; const float* bl1  = (const float*)d_in[14];
    const float* w2   = (const float*)d_in[15]; const float* b2   = (const float*)d_in[16];
    const float* wa   = (const float*)d_in[17]; const float* ba   = (const float*)d_in[18];
    const float* wra  = (const float*)d_in[19]; const float* bra  = (const float*)d_in[20];
    const float* w0   = (const float*)d_in[21]; const float* b0   = (const float*)d_in[22];
    const float* wl2  = (const float*)d_in[23]; const float* bl2  = (const float*)d_in[24];
    const float* w0b2 = (const float*)d_in[25]; const float* b0b2 = (const float*)d_in[26];
    const float* w0c2 = (const float*)d_in[27]; const float* b0c2 = (const float*)d_in[28];
    const float* wr02 = (const float*)d_in[29]; const float* br02 = (const float*)d_in[30];
    float* out = (float*)d_out;

    float *A, *Bb, *C, *x1, *x2;
    cudaGetSymbolAddress((void**)&A,  g_bufA);
    cudaGetSymbolAddress((void**)&Bb, g_bufB);
    cudaGetSymbolAddress((void**)&C,  g_bufC);
    cudaGetSymbolAddress((void**)&x1, g_x1);
    cudaGetSymbolAddress((void**)&x2, g_x2);

    // ---- stage 0 ----
    conv<3,  8, 4, 8,2,   5,  3, 0>(x,  w0a,  b0a,  A,  5, 27, 1); // (B,5,5,27)
    sl  <32, 9, 8,4,  18, 27, 1   >(A,  wl0,  bl0,  Bb, 25);       // relu (B,5,5,18)
    conv<3, 32,15, 8,4,  25, 15, 0>(Bb, w0b,  b0b,  x1, 5, 18, 1); // z -> x1
    sl  <32, 9, 8,4,  18, 27, 0   >(x,  wr0,  br0,  C,  5);        // (B,1,5,18)
    conv<1, 32, 1, 8,4,  25,  1, 1>(C,  w0c,  b0c,  x1, 5, 18, 0); // += y

    // ---- stage 1 ----
    conv<2,128,10, 8,8,  75, 50, 0>(x1, w1,   b1,   A,  5, 18, 0); // (B,75,4,18)
    sl  <16, 6, 8,4,  10, 18, 1   >(A,  wl1,  bl1,  Bb, 300);      // relu (B,75,4,10)
    conv<2,128,10, 8,8, 125,150, 0>(Bb, w2,   b2,   x2, 4, 10, 0); // z -> x2
    sl  <16, 6, 8,4,  10, 18, 0   >(x1, wra,  bra,  C,  125);      // (B,25,5,10)
    conv<3,128,16, 8,8, 125, 75, 1>(C,  wa,   ba,   x2, 5, 10, 0); // += y

    // ---- stage 2 ----
    conv<2, 64,25, 8,8, 300,250, 0>(x2, w0,   b0,   A,  3, 10, 0); // (B,300,2,10)
    sl  < 8,10, 8,2,   5, 10, 1   >(A,  wl2,  bl2,  Bb, 600);      // relu (B,300,2,5)
    conv<2,128,24, 8,8, 512,600, 0>(Bb, w0b2, b0b2, out,2,  5, 0); // z -> out
    sl  < 8,10, 8,2,   5, 10, 0   >(x2, wr02, br02, C,  375);      // (B,125,3,5)
    conv<3,128,24, 8,8, 512,375, 1>(C,  w0c2, b0c2, out,3,  5, 0); // += y
}